// round 3
// baseline (speedup 1.0000x reference)
#include <cuda_runtime.h>

#define NMAX 1000000
#define CC 16
#define KS 9
#define CPAD 24            // padded output-stride per (j,c) weight row (bank-conflict-free)
#define GRID_CONV 592      // 148 SMs * 4
#define TPB 256            // 8 warps

__device__ float g_z1[(size_t)NMAX * CC];
__device__ float g_z2[(size_t)NMAX * CC];
__device__ float g_stats[64];  // [0:16) sum1 [16:32) sumsq1 [32:48) sum2 [48:64) sumsq2

typedef unsigned long long ull;
typedef unsigned int uint;

// ---- packed f32x2 helpers ----
__device__ __forceinline__ ull pack2(float lo, float hi) {
    ull d;
    asm("mov.b64 %0, {%1, %2};" : "=l"(d) : "r"(__float_as_uint(lo)), "r"(__float_as_uint(hi)));
    return d;
}
__device__ __forceinline__ ull bcast2(float x) {
    ull d;
    asm("mov.b64 %0, {%1, %1};" : "=l"(d) : "r"(__float_as_uint(x)));
    return d;
}
__device__ __forceinline__ void fma2(ull& d, ull a, ull b) {
    asm("fma.rn.f32x2 %0, %1, %2, %0;" : "+l"(d) : "l"(a), "l"(b));
}
__device__ __forceinline__ ull add2(ull a, ull b) {
    ull d; asm("add.rn.f32x2 %0, %1, %2;" : "=l"(d) : "l"(a), "l"(b)); return d;
}
__device__ __forceinline__ ull mul2(ull a, ull b) {
    ull d; asm("mul.rn.f32x2 %0, %1, %2;" : "=l"(d) : "l"(a), "l"(b)); return d;
}
__device__ __forceinline__ float2 unpack2(ull v) {
    uint lo, hi;
    asm("mov.b64 {%0, %1}, %2;" : "=r"(lo), "=r"(hi) : "l"(v));
    return make_float2(__uint_as_float(lo), __uint_as_float(hi));
}
__device__ __forceinline__ ull shfl_xor64(ull v, int m) {
    uint lo, hi;
    asm("mov.b64 {%0, %1}, %2;" : "=r"(lo), "=r"(hi) : "l"(v));
    lo = __shfl_xor_sync(0xffffffffu, lo, m);
    hi = __shfl_xor_sync(0xffffffffu, hi, m);
    ull d;
    asm("mov.b64 %0, {%1, %2};" : "=l"(d) : "r"(lo), "r"(hi));
    return d;
}
__device__ __forceinline__ float leaky(float x) { return fmaxf(x, 0.2f * x); }

__global__ void k0_init() {
    if (threadIdx.x < 64) g_stats[threadIdx.x] = 0.0f;
}

// ---------------------------------------------------------------------------
// Conv core (4 lanes per point).  Lane q owns input channels [4q, 4q+4).
// Weight staged as ws[(j*16 + c)*CPAD + o]  (o = 0..15 contiguous).
// After quad reduce-scatter lane q holds outputs [m, m+4), m = 8*(q&1)+4*(q>>1).
// ---------------------------------------------------------------------------

__global__ __launch_bounds__(TPB, 2) void k1_conv1(
    const float* __restrict__ data, const int* __restrict__ ind,
    const float* __restrict__ w1, const float* __restrict__ b1, int N)
{
    __shared__ __align__(16) float ws[KS * CC * CPAD];
    __shared__ float bsh[CC];
    for (int i = threadIdx.x; i < KS * CC * CC; i += TPB) {
        int j = i >> 8, c = (i >> 4) & 15, o = i & 15;
        ws[(j * CC + c) * CPAD + o] = w1[(c * CC + o) * KS + j];
    }
    if (threadIdx.x < CC) bsh[threadIdx.x] = b1[threadIdx.x];
    __syncthreads();

    const int lane = threadIdx.x & 31;
    const int q = lane & 3;
    const int sel1 = lane & 1;
    const int sel2 = (lane >> 1) & 1;
    const int m = (sel1 << 3) + (sel2 << 2);

    const ull bias0 = pack2(bsh[m], bsh[m + 1]);
    const ull bias1 = pack2(bsh[m + 2], bsh[m + 3]);

    const int warp_global = blockIdx.x * (TPB / 32) + (threadIdx.x >> 5);
    const int wstride = GRID_CONV * (TPB / 32) * 8;
    const float4* __restrict__ d4 = reinterpret_cast<const float4*>(data);
    const float* __restrict__ wq = ws + (q * 4) * CPAD;

    ull sA = 0, sB = 0, qA = 0, qB = 0;

    for (int base = warp_global * 8; base < N; base += wstride) {
        int p = base + (lane >> 2);

        int idx[KS];
#pragma unroll
        for (int j = 0; j < KS; ++j) idx[j] = __ldg(ind + p * KS + j);
        float4 r[KS];
#pragma unroll
        for (int j = 0; j < KS; ++j) r[j] = __ldg(d4 + idx[j] * 4 + q);

        ull a[8];
#pragma unroll
        for (int k = 0; k < 8; ++k) a[k] = 0ull;

#pragma unroll
        for (int j = 0; j < KS; ++j) {
            const float xc[4] = {r[j].x, r[j].y, r[j].z, r[j].w};
#pragma unroll
            for (int i = 0; i < 4; ++i) {
                ull xb = bcast2(xc[i]);
                const ulonglong2* wv = reinterpret_cast<const ulonglong2*>(
                    wq + j * (CC * CPAD) + i * CPAD);
                ulonglong2 w0 = wv[0], w1v = wv[1], w2 = wv[2], w3 = wv[3];
                fma2(a[0], xb, w0.x);  fma2(a[1], xb, w0.y);
                fma2(a[2], xb, w1v.x); fma2(a[3], xb, w1v.y);
                fma2(a[4], xb, w2.x);  fma2(a[5], xb, w2.y);
                fma2(a[6], xb, w3.x);  fma2(a[7], xb, w3.y);
            }
        }

        // quad reduce-scatter: round 1 (xor 1)
        ull b4[4];
#pragma unroll
        for (int k = 0; k < 4; ++k) {
            ull send = sel1 ? a[k] : a[k + 4];
            ull got = shfl_xor64(send, 1);
            ull keep = sel1 ? a[k + 4] : a[k];
            b4[k] = add2(keep, got);
        }
        // round 2 (xor 2)
        ull z0, z1;
        {
            ull send = sel2 ? b4[0] : b4[2];
            ull got = shfl_xor64(send, 2);
            z0 = add2(sel2 ? b4[2] : b4[0], got);
            send = sel2 ? b4[1] : b4[3];
            got = shfl_xor64(send, 2);
            z1 = add2(sel2 ? b4[3] : b4[1], got);
        }
        z0 = add2(z0, bias0);
        z1 = add2(z1, bias1);

        float2 u0 = unpack2(z0), u1 = unpack2(z1);
        reinterpret_cast<float4*>(g_z1 + (size_t)p * CC + m)[0] =
            make_float4(u0.x, u0.y, u1.x, u1.y);

        sA = add2(sA, z0); sB = add2(sB, z1);
        qA = add2(qA, mul2(z0, z0)); qB = add2(qB, mul2(z1, z1));
    }

    // cross-point reduce (lanes with same q across 8 points)
#pragma unroll
    for (int off = 4; off <= 16; off <<= 1) {
        sA = add2(sA, shfl_xor64(sA, off));
        sB = add2(sB, shfl_xor64(sB, off));
        qA = add2(qA, shfl_xor64(qA, off));
        qB = add2(qB, shfl_xor64(qB, off));
    }
    if (lane < 4) {
        float2 s0 = unpack2(sA), s1 = unpack2(sB);
        float2 t0 = unpack2(qA), t1 = unpack2(qB);
        atomicAdd(&g_stats[m],     s0.x); atomicAdd(&g_stats[m + 1], s0.y);
        atomicAdd(&g_stats[m + 2], s1.x); atomicAdd(&g_stats[m + 3], s1.y);
        atomicAdd(&g_stats[16 + m],     t0.x); atomicAdd(&g_stats[16 + m + 1], t0.y);
        atomicAdd(&g_stats[16 + m + 2], t1.x); atomicAdd(&g_stats[16 + m + 3], t1.y);
    }
}

__global__ __launch_bounds__(TPB, 2) void k2_conv2(
    const int* __restrict__ ind, const float* __restrict__ w2,
    const float* __restrict__ gamma1, const float* __restrict__ beta1,
    int N, float invN)
{
    __shared__ __align__(16) float ws[KS * CC * CPAD];
    __shared__ float a1s[CC], c1s[CC];
    for (int i = threadIdx.x; i < KS * CC * CC; i += TPB) {
        int j = i >> 8, c = (i >> 4) & 15, o = i & 15;
        ws[(j * CC + c) * CPAD + o] = w2[(c * CC + o) * KS + j];
    }
    if (threadIdx.x < CC) {
        int o = threadIdx.x;
        float mean = g_stats[o] * invN;
        float var  = g_stats[16 + o] * invN - mean * mean;
        float a = gamma1[o] * rsqrtf(var + 1e-5f);
        a1s[o] = a;
        c1s[o] = fmaf(-mean, a, beta1[o]);
    }
    __syncthreads();

    const int lane = threadIdx.x & 31;
    const int q = lane & 3;
    const int sel1 = lane & 1;
    const int sel2 = (lane >> 1) & 1;
    const int m = (sel1 << 3) + (sel2 << 2);

    // BN1 affine for this lane's input-channel quarter
    float a1v[4], c1v[4];
#pragma unroll
    for (int i = 0; i < 4; ++i) { a1v[i] = a1s[q * 4 + i]; c1v[i] = c1s[q * 4 + i]; }

    const int warp_global = blockIdx.x * (TPB / 32) + (threadIdx.x >> 5);
    const int wstride = GRID_CONV * (TPB / 32) * 8;
    const float4* __restrict__ z14 = reinterpret_cast<const float4*>(g_z1);
    const float* __restrict__ wq = ws + (q * 4) * CPAD;

    ull sA = 0, sB = 0, qA = 0, qB = 0;

    for (int base = warp_global * 8; base < N; base += wstride) {
        int p = base + (lane >> 2);

        int idx[KS];
#pragma unroll
        for (int j = 0; j < KS; ++j) idx[j] = __ldg(ind + p * KS + j);
        float4 r[KS];
#pragma unroll
        for (int j = 0; j < KS; ++j) r[j] = z14[idx[j] * 4 + q];

        ull a[8];
#pragma unroll
        for (int k = 0; k < 8; ++k) a[k] = 0ull;

#pragma unroll
        for (int j = 0; j < KS; ++j) {
            float xc[4] = {r[j].x, r[j].y, r[j].z, r[j].w};
#pragma unroll
            for (int i = 0; i < 4; ++i)
                xc[i] = leaky(fmaf(a1v[i], xc[i], c1v[i]));
#pragma unroll
            for (int i = 0; i < 4; ++i) {
                ull xb = bcast2(xc[i]);
                const ulonglong2* wv = reinterpret_cast<const ulonglong2*>(
                    wq + j * (CC * CPAD) + i * CPAD);
                ulonglong2 w0 = wv[0], w1v = wv[1], w2v = wv[2], w3 = wv[3];
                fma2(a[0], xb, w0.x);  fma2(a[1], xb, w0.y);
                fma2(a[2], xb, w1v.x); fma2(a[3], xb, w1v.y);
                fma2(a[4], xb, w2v.x); fma2(a[5], xb, w2v.y);
                fma2(a[6], xb, w3.x);  fma2(a[7], xb, w3.y);
            }
        }

        ull b4[4];
#pragma unroll
        for (int k = 0; k < 4; ++k) {
            ull send = sel1 ? a[k] : a[k + 4];
            ull got = shfl_xor64(send, 1);
            ull keep = sel1 ? a[k + 4] : a[k];
            b4[k] = add2(keep, got);
        }
        ull z0, z1;
        {
            ull send = sel2 ? b4[0] : b4[2];
            ull got = shfl_xor64(send, 2);
            z0 = add2(sel2 ? b4[2] : b4[0], got);
            send = sel2 ? b4[1] : b4[3];
            got = shfl_xor64(send, 2);
            z1 = add2(sel2 ? b4[3] : b4[1], got);
        }

        float2 u0 = unpack2(z0), u1 = unpack2(z1);
        reinterpret_cast<float4*>(g_z2 + (size_t)p * CC + m)[0] =
            make_float4(u0.x, u0.y, u1.x, u1.y);

        sA = add2(sA, z0); sB = add2(sB, z1);
        qA = add2(qA, mul2(z0, z0)); qB = add2(qB, mul2(z1, z1));
    }

#pragma unroll
    for (int off = 4; off <= 16; off <<= 1) {
        sA = add2(sA, shfl_xor64(sA, off));
        sB = add2(sB, shfl_xor64(sB, off));
        qA = add2(qA, shfl_xor64(qA, off));
        qB = add2(qB, shfl_xor64(qB, off));
    }
    if (lane < 4) {
        float2 s0 = unpack2(sA), s1 = unpack2(sB);
        float2 t0 = unpack2(qA), t1 = unpack2(qB);
        atomicAdd(&g_stats[32 + m],     s0.x); atomicAdd(&g_stats[32 + m + 1], s0.y);
        atomicAdd(&g_stats[32 + m + 2], s1.x); atomicAdd(&g_stats[32 + m + 3], s1.y);
        atomicAdd(&g_stats[48 + m],     t0.x); atomicAdd(&g_stats[48 + m + 1], t0.y);
        atomicAdd(&g_stats[48 + m + 2], t1.x); atomicAdd(&g_stats[48 + m + 3], t1.y);
    }
}

__global__ __launch_bounds__(256) void k3_epilogue(
    const float* __restrict__ data, const float* __restrict__ gamma2,
    const float* __restrict__ beta2, float* __restrict__ out,
    int N, float invN)
{
    __shared__ float a2s[CC], c2s[CC];
    if (threadIdx.x < CC) {
        int o = threadIdx.x;
        float mean = g_stats[32 + o] * invN;
        float var  = g_stats[48 + o] * invN - mean * mean;
        float a = gamma2[o] * rsqrtf(var + 1e-5f);
        a2s[o] = a;
        c2s[o] = fmaf(-mean, a, beta2[o]);
    }
    __syncthreads();

    int total4 = N * 4;
    const float4* z4 = reinterpret_cast<const float4*>(g_z2);
    const float4* d4 = reinterpret_cast<const float4*>(data);
    float4* o4 = reinterpret_cast<float4*>(out);
    for (int i = blockIdx.x * blockDim.x + threadIdx.x; i < total4;
         i += gridDim.x * blockDim.x) {
        float4 zv = z4[i];
        float4 dv = d4[i];
        int cb = (i & 3) * 4;
        float4 r;
        r.x = leaky(fmaf(a2s[cb + 0], zv.x, c2s[cb + 0]) + dv.x);
        r.y = leaky(fmaf(a2s[cb + 1], zv.y, c2s[cb + 1]) + dv.y);
        r.z = leaky(fmaf(a2s[cb + 2], zv.z, c2s[cb + 2]) + dv.z);
        r.w = leaky(fmaf(a2s[cb + 3], zv.w, c2s[cb + 3]) + dv.w);
        o4[i] = r;
    }
}

extern "C" void kernel_launch(void* const* d_in, const int* in_sizes, int n_in,
                              void* d_out, int out_size)
{
    const float* data   = (const float*)d_in[0];
    const int*   ind    = (const int*)d_in[1];
    const float* w1     = (const float*)d_in[2];
    const float* b1     = (const float*)d_in[3];
    const float* gamma1 = (const float*)d_in[4];
    const float* beta1  = (const float*)d_in[5];
    const float* w2     = (const float*)d_in[6];
    const float* gamma2 = (const float*)d_in[7];
    const float* beta2  = (const float*)d_in[8];

    int N = in_sizes[0] / CC;
    if (N > NMAX) N = NMAX;
    float invN = 1.0f / (float)N;

    k0_init<<<1, 64>>>();
    k1_conv1<<<GRID_CONV, TPB>>>(data, ind, w1, b1, N);
    k2_conv2<<<GRID_CONV, TPB>>>(ind, w2, gamma1, beta1, N, invN);
    k3_epilogue<<<1024, 256>>>(data, gamma2, beta2, (float*)d_out, N, invN);
}

// round 5
// speedup vs baseline: 3.6367x; 3.6367x over previous
#include <cuda_runtime.h>
#include <cuda_bf16.h>
#include <cstdint>

#define NMAX 1000000
#define CC 16
#define KS 9
#define TPB 128                 // 4 warps
#define WPC 4
#define GRID_CONV 444           // 148 SMs * 3 CTAs
#define STAGE_BYTES 9216        // per-warp: 18 chunks * 16 rows * 32B
#define SMEM_BYTES (WPC * STAGE_BYTES)

typedef unsigned int uint;

// ---------------- device scratch ----------------
__device__ float g_z1[(size_t)NMAX * CC];
__device__ float g_z2[(size_t)NMAX * CC];
__device__ uint4 g_dhl[(size_t)NMAX * 4];   // per row 64B: [hi c0-7 | hi c8-15 | lo c0-7 | lo c8-15]
__device__ uint4 g_ahl[(size_t)NMAX * 4];
__device__ float g_stats[64];               // sum1, sumsq1, sum2, sumsq2

// ---------------- helpers ----------------
__device__ __forceinline__ uint32_t smem_u32(const void* p) {
    uint32_t a;
    asm("{ .reg .u64 t; cvta.to.shared.u64 t, %1; cvt.u32.u64 %0, t; }" : "=r"(a) : "l"(p));
    return a;
}
__device__ __forceinline__ void sts128(uint32_t a, uint4 v) {
    asm volatile("st.shared.v4.b32 [%0], {%1,%2,%3,%4};"
                 :: "r"(a), "r"(v.x), "r"(v.y), "r"(v.z), "r"(v.w) : "memory");
}
__device__ __forceinline__ void ldsm4(uint32_t* a, uint32_t addr) {
    asm volatile("ldmatrix.sync.aligned.m8n8.x4.shared.b16 {%0,%1,%2,%3}, [%4];"
                 : "=r"(a[0]), "=r"(a[1]), "=r"(a[2]), "=r"(a[3]) : "r"(addr));
}
__device__ __forceinline__ void mma16816(float* c, const uint32_t* a, const uint32_t* b) {
    asm volatile("mma.sync.aligned.m16n8k16.row.col.f32.bf16.bf16.f32 "
                 "{%0,%1,%2,%3}, {%4,%5,%6,%7}, {%8,%9}, {%0,%1,%2,%3};"
                 : "+f"(c[0]), "+f"(c[1]), "+f"(c[2]), "+f"(c[3])
                 : "r"(a[0]), "r"(a[1]), "r"(a[2]), "r"(a[3]), "r"(b[0]), "r"(b[1]));
}
__device__ __forceinline__ float leaky(float x) { return fmaxf(x, 0.2f * x); }

__device__ __forceinline__ uint packhl(float x, float y, uint& lo_out) {
    __nv_bfloat16 hx = __float2bfloat16_rn(x);
    __nv_bfloat16 hy = __float2bfloat16_rn(y);
    __nv_bfloat16 lx = __float2bfloat16_rn(x - __bfloat162float(hx));
    __nv_bfloat16 ly = __float2bfloat16_rn(y - __bfloat162float(hy));
    lo_out = (uint)__bfloat16_as_ushort(lx) | ((uint)__bfloat16_as_ushort(ly) << 16);
    return (uint)__bfloat16_as_ushort(hx) | ((uint)__bfloat16_as_ushort(hy) << 16);
}

// split 8 floats -> hi uint4 + lo uint4
__device__ __forceinline__ void split8(const float* v, uint4& hi, uint4& lo) {
    uint l0, l1, l2, l3;
    hi.x = packhl(v[0], v[1], l0);
    hi.y = packhl(v[2], v[3], l1);
    hi.z = packhl(v[4], v[5], l2);
    hi.w = packhl(v[6], v[7], l3);
    lo = make_uint4(l0, l1, l2, l3);
}

// ---------------------------------------------------------------------------
// k0: zero stats + split data -> g_dhl
// ---------------------------------------------------------------------------
__global__ __launch_bounds__(256) void k0_split(const float* __restrict__ data, int N) {
    int g = blockIdx.x * 256 + threadIdx.x;
    if (g < 64) g_stats[g] = 0.0f;
    if (g >= 2 * N) return;
    int p = g >> 1, h = g & 1;   // h: which 8-channel half
    const float4* s = reinterpret_cast<const float4*>(data) + (size_t)p * 4 + h * 2;
    float4 a = s[0], b = s[1];
    float v[8] = {a.x, a.y, a.z, a.w, b.x, b.y, b.z, b.w};
    uint4 hi, lo;
    split8(v, hi, lo);
    g_dhl[(size_t)p * 4 + h] = hi;
    g_dhl[(size_t)p * 4 + 2 + h] = lo;
}

// ---------------------------------------------------------------------------
// conv via mma.sync: FIRST -> src g_dhl, out g_z1, +bias, stats[0..32)
//                    else  -> src g_ahl, out g_z2, stats[32..64)
// Each warp handles 16 points per tile. Per-warp smem staging, no block sync.
// ---------------------------------------------------------------------------
template <bool FIRST>
__global__ __launch_bounds__(TPB, 3) void conv_mma(
    const int* __restrict__ ind, const float* __restrict__ w,
    const float* __restrict__ bias, int N, int ntiles)
{
    extern __shared__ __align__(16) char smraw[];
    const int tid = threadIdx.x, wid = tid >> 5, lane = tid & 31;
    const uint32_t stage = smem_u32(smraw) + (uint32_t)wid * STAGE_BYTES;

    const uint4* __restrict__ src = FIRST ? g_dhl : g_ahl;
    float* __restrict__ zout = FIRST ? g_z1 : g_z2;

    const int t4 = lane & 3;        // k-pair / column group
    const int nrow = lane >> 2;     // n within 8-frag / point row

    // ---- B fragments in registers (hi & lo), 9 chunks x 2 n-frags x 2 regs ----
    uint32_t bh[KS][2][2], bl[KS][2][2];
#pragma unroll
    for (int j = 0; j < KS; ++j) {
#pragma unroll
        for (int nf = 0; nf < 2; ++nf) {
            int n = nf * 8 + nrow;
            int k0 = t4 * 2;
            float w00 = __ldg(w + ((k0 + 0) * CC + n) * KS + j);
            float w01 = __ldg(w + ((k0 + 1) * CC + n) * KS + j);
            float w10 = __ldg(w + ((k0 + 8) * CC + n) * KS + j);
            float w11 = __ldg(w + ((k0 + 9) * CC + n) * KS + j);
            uint lo;
            bh[j][nf][0] = packhl(w00, w01, lo); bl[j][nf][0] = lo;
            bh[j][nf][1] = packhl(w10, w11, lo); bl[j][nf][1] = lo;
        }
    }

    // bias for this lane's channels: {2t, 2t+1} (nf0), {2t+8, 2t+9} (nf1)
    float bia[4] = {0, 0, 0, 0};
    if (FIRST) {
        bia[0] = __ldg(bias + 2 * t4);
        bia[1] = __ldg(bias + 2 * t4 + 1);
        bia[2] = __ldg(bias + 2 * t4 + 8);
        bia[3] = __ldg(bias + 2 * t4 + 9);
    }

    // ldmatrix per-lane address offset within a 512B chunk
    const uint32_t lr = lane & 15;
    const uint32_t lseg = (uint32_t)(lane >> 4) ^ ((lr >> 2) & 1);
    const uint32_t lmoff = lr * 32 + lseg * 16;

    float s[4] = {0, 0, 0, 0}, q[4] = {0, 0, 0, 0};

    const int wstep = GRID_CONV * WPC;
    for (int t = blockIdx.x * WPC + wid; t < ntiles; t += wstep) {
        const int base = t * 16;

        // ---- gather: 144 (pt,j) pairs, each lane stages whole 64B split-row ----
#pragma unroll
        for (int i = 0; i < 5; ++i) {
            int pid = i * 32 + lane;
            if (pid < 144) {
                int pt = pid & 15, j = pid >> 4;
                int pg = base + pt;
                int idx = (pg < N) ? __ldg(ind + pg * KS + j) : 0;
                const uint4* row = src + (size_t)idx * 4;
                uint4 h0 = __ldg(row), h1 = __ldg(row + 1);
                uint4 l0 = __ldg(row + 2), l1 = __ldg(row + 3);
                uint32_t x = ((pt >> 2) & 1) << 4;
                uint32_t rb = stage + (uint32_t)j * 512 + (uint32_t)pt * 32;
                sts128(rb + (0 ^ x), h0);
                sts128(rb + (16 ^ x), h1);
                rb += KS * 512;
                sts128(rb + (0 ^ x), l0);
                sts128(rb + (16 ^ x), l1);
            }
        }
        __syncwarp();

        // ---- MMA: 9 chunks x (Ahi*Bhi + Ahi*Blo + Alo*Bhi) x 2 n-frags ----
        float c0[4] = {0, 0, 0, 0}, c1[4] = {0, 0, 0, 0};
#pragma unroll
        for (int j = 0; j < KS; ++j) {
            uint32_t ah[4], al[4];
            ldsm4(ah, stage + (uint32_t)j * 512 + lmoff);
            ldsm4(al, stage + (uint32_t)(KS + j) * 512 + lmoff);
            mma16816(c0, ah, bh[j][0]);
            mma16816(c1, ah, bh[j][1]);
            mma16816(c0, ah, bl[j][0]);
            mma16816(c1, ah, bl[j][1]);
            mma16816(c0, al, bh[j][0]);
            mma16816(c1, al, bh[j][1]);
        }
        __syncwarp();

        // ---- epilogue: bias, z store, stats ----
        int pA = base + nrow;      // c[0], c[1]
        int pB = pA + 8;           // c[2], c[3]
        float zA0 = c0[0] + bia[0], zA1 = c0[1] + bia[1];
        float zA2 = c1[0] + bia[2], zA3 = c1[1] + bia[3];
        float zB0 = c0[2] + bia[0], zB1 = c0[3] + bia[1];
        float zB2 = c1[2] + bia[2], zB3 = c1[3] + bia[3];

        if (pA < N) {
            float* zr = zout + (size_t)pA * CC + 2 * t4;
            reinterpret_cast<float2*>(zr)[0] = make_float2(zA0, zA1);
            reinterpret_cast<float2*>(zr + 8)[0] = make_float2(zA2, zA3);
            s[0] += zA0; s[1] += zA1; s[2] += zA2; s[3] += zA3;
            q[0] += zA0 * zA0; q[1] += zA1 * zA1; q[2] += zA2 * zA2; q[3] += zA3 * zA3;
        }
        if (pB < N) {
            float* zr = zout + (size_t)pB * CC + 2 * t4;
            reinterpret_cast<float2*>(zr)[0] = make_float2(zB0, zB1);
            reinterpret_cast<float2*>(zr + 8)[0] = make_float2(zB2, zB3);
            s[0] += zB0; s[1] += zB1; s[2] += zB2; s[3] += zB3;
            q[0] += zB0 * zB0; q[1] += zB1 * zB1; q[2] += zB2 * zB2; q[3] += zB3 * zB3;
        }
    }

    // ---- stats: reduce across lanes sharing t4, then 4 lanes do atomics ----
#pragma unroll
    for (int off = 4; off <= 16; off <<= 1) {
#pragma unroll
        for (int k = 0; k < 4; ++k) {
            s[k] += __shfl_xor_sync(0xffffffffu, s[k], off);
            q[k] += __shfl_xor_sync(0xffffffffu, q[k], off);
        }
    }
    if (lane < 4) {
        const int soff = FIRST ? 0 : 32;
        int ch[4] = {2 * lane, 2 * lane + 1, 2 * lane + 8, 2 * lane + 9};
#pragma unroll
        for (int k = 0; k < 4; ++k) {
            atomicAdd(&g_stats[soff + ch[k]], s[k]);
            atomicAdd(&g_stats[soff + 16 + ch[k]], q[k]);
        }
    }
}

// ---------------------------------------------------------------------------
// k1b: act = leaky(bn1(z1)); split -> g_ahl
// ---------------------------------------------------------------------------
__global__ __launch_bounds__(256) void k1b_actsplit(
    const float* __restrict__ gamma1, const float* __restrict__ beta1, int N, float invN)
{
    __shared__ float as_[CC], cs_[CC];
    if (threadIdx.x < CC) {
        int o = threadIdx.x;
        float mean = g_stats[o] * invN;
        float var = g_stats[16 + o] * invN - mean * mean;
        float a = gamma1[o] * rsqrtf(var + 1e-5f);
        as_[o] = a;
        cs_[o] = fmaf(-mean, a, beta1[o]);
    }
    __syncthreads();
    int g = blockIdx.x * 256 + threadIdx.x;
    if (g >= 2 * N) return;
    int p = g >> 1, h = g & 1;
    const float4* sp = reinterpret_cast<const float4*>(g_z1) + (size_t)p * 4 + h * 2;
    float4 a = sp[0], b = sp[1];
    float v[8] = {a.x, a.y, a.z, a.w, b.x, b.y, b.z, b.w};
#pragma unroll
    for (int k = 0; k < 8; ++k) {
        int c = h * 8 + k;
        v[k] = leaky(fmaf(as_[c], v[k], cs_[c]));
    }
    uint4 hi, lo;
    split8(v, hi, lo);
    g_ahl[(size_t)p * 4 + h] = hi;
    g_ahl[(size_t)p * 4 + 2 + h] = lo;
}

// ---------------------------------------------------------------------------
// k3: out = leaky(bn2(z2) + data)
// ---------------------------------------------------------------------------
__global__ __launch_bounds__(256) void k3_epilogue(
    const float* __restrict__ data, const float* __restrict__ gamma2,
    const float* __restrict__ beta2, float* __restrict__ out, int N, float invN)
{
    __shared__ float a2s[CC], c2s[CC];
    if (threadIdx.x < CC) {
        int o = threadIdx.x;
        float mean = g_stats[32 + o] * invN;
        float var = g_stats[48 + o] * invN - mean * mean;
        float a = gamma2[o] * rsqrtf(var + 1e-5f);
        a2s[o] = a;
        c2s[o] = fmaf(-mean, a, beta2[o]);
    }
    __syncthreads();
    int total4 = N * 4;
    const float4* z4 = reinterpret_cast<const float4*>(g_z2);
    const float4* d4 = reinterpret_cast<const float4*>(data);
    float4* o4 = reinterpret_cast<float4*>(out);
    for (int i = blockIdx.x * blockDim.x + threadIdx.x; i < total4;
         i += gridDim.x * blockDim.x) {
        float4 zv = z4[i];
        float4 dv = d4[i];
        int cb = (i & 3) * 4;
        float4 r;
        r.x = leaky(fmaf(a2s[cb + 0], zv.x, c2s[cb + 0]) + dv.x);
        r.y = leaky(fmaf(a2s[cb + 1], zv.y, c2s[cb + 1]) + dv.y);
        r.z = leaky(fmaf(a2s[cb + 2], zv.z, c2s[cb + 2]) + dv.z);
        r.w = leaky(fmaf(a2s[cb + 3], zv.w, c2s[cb + 3]) + dv.w);
        o4[i] = r;
    }
}

extern "C" void kernel_launch(void* const* d_in, const int* in_sizes, int n_in,
                              void* d_out, int out_size)
{
    const float* data   = (const float*)d_in[0];
    const int*   ind    = (const int*)d_in[1];
    const float* w1     = (const float*)d_in[2];
    const float* b1     = (const float*)d_in[3];
    const float* gamma1 = (const float*)d_in[4];
    const float* beta1  = (const float*)d_in[5];
    const float* w2     = (const float*)d_in[6];
    const float* gamma2 = (const float*)d_in[7];
    const float* beta2  = (const float*)d_in[8];

    int N = in_sizes[0] / CC;
    if (N > NMAX) N = NMAX;
    float invN = 1.0f / (float)N;
    int ntiles = (N + 15) / 16;
    int gsplit = (2 * N + 255) / 256;

    k0_split<<<gsplit, 256>>>(data, N);
    conv_mma<true><<<GRID_CONV, TPB, SMEM_BYTES>>>(ind, w1, b1, N, ntiles);
    k1b_actsplit<<<gsplit, 256>>>(gamma1, beta1, N, invN);
    conv_mma<false><<<GRID_CONV, TPB, SMEM_BYTES>>>(ind, w2, nullptr, N, ntiles);
    k3_epilogue<<<1024, 256>>>(data, gamma2, beta2, (float*)d_out, N, invN);
}